// round 17
// baseline (speedup 1.0000x reference)
#include <cuda_runtime.h>
#include <cuda_fp16.h>
#include <cstdint>

#define N_NODES 50000
#define N_EDGES 160000
#define DIM     512
#define N_GRAPHS 64
#define EPSV    1e-5f

// GEMM tiling: BM=128, BN=128, BK=32, 3-stage cp.async, 8 warps, warp tile 64x32, 2 CTAs/SM
#define AS_STR 36
#define BS_STR 136
#define AS_ELE (128 * AS_STR)
#define BS_ELE (32 * BS_STR)
#define NSTAGE 3
#define SMEM_BYTES (NSTAGE * (AS_ELE + BS_ELE) * 4)   // 107520 B

// gather: padded CSR (32 slots/dst), full row per warp
#define SLOTS 32
#define GW 8

struct Edge { int src; float w; };

// ---- scratch (static __device__: allocation-free) ----
__device__ __half g_xw [(size_t)N_NODES * DIM];      // x @ W in fp16 (50MB: L2-resident)
__device__ float  g_acc[(size_t)N_NODES * DIM];
__device__ float  g_deg[N_NODES];
__device__ int    g_slot[N_NODES];
__device__ Edge   g_csr[(size_t)N_NODES * SLOTS];
__device__ float  g_sum[N_GRAPHS * DIM];
__device__ float  g_sq [N_GRAPHS * DIM];
__device__ float  g_cnt[N_GRAPHS];
__device__ int    g_batch [N_NODES];

// ---------------------------------------------------------------- init
__global__ void k_init() {
    int i = blockIdx.x * blockDim.x + threadIdx.x;
    if (i < N_NODES) { g_deg[i] = 1.0f; g_slot[i] = 0; }
    if (i < N_GRAPHS * DIM) { g_sum[i] = 0.f; g_sq[i] = 0.f; }
    if (i < N_GRAPHS) g_cnt[i] = 0.f;
}

// ---------------------------------------------------------------- convert + degree + CSR fill (fused)
__global__ void k_convert(const void* __restrict__ ei, const void* __restrict__ batch,
                          const float* __restrict__ w) {
    __shared__ int s64;
    const int tid = threadIdx.x;
    if (tid == 0) {
        const long long* q = (const long long*)ei;
        int ok = 1;
#pragma unroll
        for (int i = 0; i < 8; i++) { long long v = q[i]; if (v < 0 || v >= N_NODES) ok = 0; }
        s64 = ok;
    }
    __syncthreads();
    const int is64 = s64;
    const int e = blockIdx.x * blockDim.x + tid;
    if (e < N_EDGES) {
        int r, c;
        if (is64) { r = (int)((const long long*)ei)[e]; c = (int)((const long long*)ei)[N_EDGES + e]; }
        else      { r = ((const int*)ei)[e];            c = ((const int*)ei)[N_EDGES + e]; }
        r = min(max(r, 0), N_NODES - 1);
        c = min(max(c, 0), N_NODES - 1);
        const float we = w[e];
        atomicAdd(&g_deg[c], we);
        const int slot = atomicAdd(&g_slot[c], 1);
        if (slot < SLOTS) {
            Edge ed; ed.src = r; ed.w = we;
            g_csr[(size_t)c * SLOTS + slot] = ed;
        }
    }
    if (e < N_NODES) {
        int bv = is64 ? (int)((const long long*)batch)[e] : ((const int*)batch)[e];
        g_batch[e] = min(max(bv, 0), N_GRAPHS - 1);
    }
}

// ---------------------------------------------------------------- helpers
__device__ __forceinline__ void cpasync16(uint32_t dst, const void* src) {
    asm volatile("cp.async.cg.shared.global [%0], [%1], 16;" :: "r"(dst), "l"(src));
}
#define CP_COMMIT()  asm volatile("cp.async.commit_group;" ::: "memory")
#define CP_WAIT(n)   asm volatile("cp.async.wait_group %0;" :: "n"(n) : "memory")
__device__ __forceinline__ uint32_t smem_u32(const void* p) {
    uint32_t a;
    asm("{ .reg .u64 t; cvta.to.shared.u64 t, %1; cvt.u32.u64 %0, t; }" : "=r"(a) : "l"(p));
    return a;
}
__device__ __forceinline__ void mma_tf32(float* d, const uint32_t* a, const uint32_t* b) {
    asm volatile(
        "mma.sync.aligned.m16n8k8.row.col.f32.tf32.tf32.f32 "
        "{%0,%1,%2,%3},{%4,%5,%6,%7},{%8,%9},{%0,%1,%2,%3};\n"
        : "+f"(d[0]), "+f"(d[1]), "+f"(d[2]), "+f"(d[3])
        : "r"(a[0]), "r"(a[1]), "r"(a[2]), "r"(a[3]), "r"(b[0]), "r"(b[1]));
}
__device__ __forceinline__ void red4(float* p, float4 v) {
    asm volatile("red.global.add.v4.f32 [%0], {%1,%2,%3,%4};"
                 :: "l"(p), "f"(v.x), "f"(v.y), "f"(v.z), "f"(v.w) : "memory");
}
// accumulate 8 halves (as uint4) scaled by c into two float4s
__device__ __forceinline__ void acc8h(float4& a0, float4& a1, uint4 u, float c) {
    const float2 p0 = __half22float2(*(const __half2*)&u.x);
    const float2 p1 = __half22float2(*(const __half2*)&u.y);
    const float2 p2 = __half22float2(*(const __half2*)&u.z);
    const float2 p3 = __half22float2(*(const __half2*)&u.w);
    a0.x += p0.x * c; a0.y += p0.y * c; a0.z += p1.x * c; a0.w += p1.y * c;
    a1.x += p2.x * c; a1.y += p2.y * c; a1.z += p3.x * c; a1.w += p3.y * c;
}

// ---------------------------------------------------------------- GEMM (epilogue writes fp16 g_xw)
__global__ void __launch_bounds__(256, 2) k_gemm(
    const float* __restrict__ A,
    const float* __restrict__ B)
{
    extern __shared__ float smem[];
    const uint32_t sbase = smem_u32(smem);
    const int tid  = threadIdx.x;
    const int lane = tid & 31;
    const int warp = tid >> 5;
    const int wm = warp >> 2;
    const int wn = warp & 3;
    const int m0 = blockIdx.y * 128;
    const int n0 = blockIdx.x * 128;

    float acc[4][4][4];
#pragma unroll
    for (int i = 0; i < 4; i++)
#pragma unroll
        for (int j = 0; j < 4; j++)
#pragma unroll
            for (int c = 0; c < 4; c++) acc[i][j][c] = 0.f;

#define ISSUE(KT) do {                                                           \
        const int kk = (KT) * 32;                                                \
        const uint32_t sa = sbase + ((KT) % NSTAGE) * (AS_ELE * 4);              \
        const uint32_t sbb = sbase + (NSTAGE * AS_ELE + ((KT) % NSTAGE) * BS_ELE) * 4; \
        _Pragma("unroll")                                                        \
        for (int i = 0; i < 4; i++) {                                            \
            const int idx = tid + i * 256;                                       \
            const int row = idx >> 3, col = (idx & 7) * 4;                       \
            int gm = m0 + row;                                                   \
            if (gm >= N_NODES) gm = N_NODES - 1;                                 \
            cpasync16(sa + (uint32_t)(row * AS_STR + col) * 4,                   \
                      A + (size_t)gm * 512 + kk + col);                          \
        }                                                                        \
        _Pragma("unroll")                                                        \
        for (int i = 0; i < 4; i++) {                                            \
            const int idx = tid + i * 256;                                       \
            const int row = idx >> 5, col = (idx & 31) * 4;                      \
            cpasync16(sbb + (uint32_t)(row * BS_STR + col) * 4,                  \
                      B + (size_t)(kk + row) * 512 + n0 + col);                  \
        }                                                                        \
        CP_COMMIT();                                                             \
    } while (0)

    ISSUE(0);
    ISSUE(1);

#pragma unroll 1
    for (int kt = 0; kt < 16; kt++) {
        CP_WAIT(1);
        __syncthreads();
        if (kt + 2 < 16) ISSUE(kt + 2);

        const float* as = smem + (kt % NSTAGE) * AS_ELE;
        const float* bs = smem + NSTAGE * AS_ELE + (kt % NSTAGE) * BS_ELE;
#pragma unroll
        for (int ks = 0; ks < 4; ks++) {
            uint32_t af[4][4], bf[4][2];
            const int kk = ks * 8 + (lane & 3);
#pragma unroll
            for (int i = 0; i < 4; i++) {
                const int r = wm * 64 + i * 16 + (lane >> 2);
                af[i][0] = __float_as_uint(as[r * AS_STR + kk]);
                af[i][1] = __float_as_uint(as[(r + 8) * AS_STR + kk]);
                af[i][2] = __float_as_uint(as[r * AS_STR + kk + 4]);
                af[i][3] = __float_as_uint(as[(r + 8) * AS_STR + kk + 4]);
            }
#pragma unroll
            for (int j = 0; j < 4; j++) {
                const int c = wn * 32 + j * 8 + (lane >> 2);
                bf[j][0] = __float_as_uint(bs[kk * BS_STR + c]);
                bf[j][1] = __float_as_uint(bs[(kk + 4) * BS_STR + c]);
            }
#pragma unroll
            for (int i = 0; i < 4; i++)
#pragma unroll
                for (int j = 0; j < 4; j++)
                    mma_tf32(acc[i][j], af[i], bf[j]);
        }
    }

    // epilogue: write xw (fp16)
#pragma unroll
    for (int i = 0; i < 4; i++) {
        const int rbase = m0 + wm * 64 + i * 16 + (lane >> 2);
#pragma unroll
        for (int h = 0; h < 2; h++) {
            const int gm = rbase + h * 8;
            if (gm < N_NODES) {
#pragma unroll
                for (int j = 0; j < 4; j++) {
                    const int cb = n0 + wn * 32 + j * 8 + ((lane & 3) << 1);
                    const __half2 hv = __floats2half2_rn(acc[i][j][h * 2 + 0],
                                                         acc[i][j][h * 2 + 1]);
                    *(__half2*)(g_xw + (size_t)gm * 512 + cb) = hv;
                }
            }
        }
    }
#undef ISSUE
}

// ---------------------------------------------------------------- CSR gather: full row per warp
// Lane t owns dims [t*8, t*8+8) and [256+t*8, ...): 2 x uint4 fp16 loads/edge.
// Stats: s_sum only (reducer squares it for sumsq) -> 16.5KB smem, ~2x occ.
__global__ void __launch_bounds__(256) k_gather(const float* __restrict__ node,
                                                const float* __restrict__ bias) {
    __shared__ float s_sum[GW][DIM];
    __shared__ int   s_gid[GW];
    const int w = threadIdx.x >> 5;
    const int t = threadIdx.x & 31;
    const int n = blockIdx.x * GW + w;
    const int d0 = t * 8;               // first 8-dim chunk; second at 256+d0

    float4 a[4];
#pragma unroll
    for (int q = 0; q < 4; q++) a[q] = make_float4(0.f, 0.f, 0.f, 0.f);
    int g = -1;
    if (n < N_NODES) {
        g = g_batch[n];
        const int cnt = min(g_slot[n], SLOTS);
        const float invdeg = 1.0f / g_deg[n];
        const float rs_n = rsqrtf(g_deg[n]);
        const size_t nb = (size_t)n * DIM;
        // skip + bias
#pragma unroll
        for (int h = 0; h < 2; h++) {
            const int dd = h * 256 + d0;
            const float4 n0v = __ldcs((const float4*)(node + nb + dd));
            const float4 n1v = __ldcs((const float4*)(node + nb + dd + 4));
            const float4 b0 = *(const float4*)(bias + dd);
            const float4 b1 = *(const float4*)(bias + dd + 4);
            a[h * 2 + 0].x = n0v.x + b0.x; a[h * 2 + 0].y = n0v.y + b0.y;
            a[h * 2 + 0].z = n0v.z + b0.z; a[h * 2 + 0].w = n0v.w + b0.w;
            a[h * 2 + 1].x = n1v.x + b1.x; a[h * 2 + 1].y = n1v.y + b1.y;
            a[h * 2 + 1].z = n1v.z + b1.z; a[h * 2 + 1].w = n1v.w + b1.w;
        }
        // self-loop term
        acc8h(a[0], a[1], *(const uint4*)(g_xw + nb + d0), invdeg);
        acc8h(a[2], a[3], *(const uint4*)(g_xw + nb + 256 + d0), invdeg);

        const size_t base = (size_t)n * SLOTS;
        int i = 0;
        for (; i + 2 <= cnt; i += 2) {
            const Edge e0 = g_csr[base + i + 0];
            const Edge e1 = g_csr[base + i + 1];
            const float c0 = e0.w * rsqrtf(g_deg[e0.src]) * rs_n;
            const float c1 = e1.w * rsqrtf(g_deg[e1.src]) * rs_n;
            const size_t o0 = (size_t)e0.src * DIM;
            const size_t o1 = (size_t)e1.src * DIM;
            const uint4 u00 = *(const uint4*)(g_xw + o0 + d0);
            const uint4 u01 = *(const uint4*)(g_xw + o0 + 256 + d0);
            const uint4 u10 = *(const uint4*)(g_xw + o1 + d0);
            const uint4 u11 = *(const uint4*)(g_xw + o1 + 256 + d0);
            acc8h(a[0], a[1], u00, c0);
            acc8h(a[2], a[3], u01, c0);
            acc8h(a[0], a[1], u10, c1);
            acc8h(a[2], a[3], u11, c1);
        }
        if (i < cnt) {
            const Edge e0 = g_csr[base + i];
            const float c0 = e0.w * rsqrtf(g_deg[e0.src]) * rs_n;
            const size_t o0 = (size_t)e0.src * DIM;
            acc8h(a[0], a[1], *(const uint4*)(g_xw + o0 + d0), c0);
            acc8h(a[2], a[3], *(const uint4*)(g_xw + o0 + 256 + d0), c0);
        }
        __stcs((float4*)(g_acc + nb + d0), a[0]);
        __stcs((float4*)(g_acc + nb + d0 + 4), a[1]);
        __stcs((float4*)(g_acc + nb + 256 + d0), a[2]);
        __stcs((float4*)(g_acc + nb + 256 + d0 + 4), a[3]);
        if (t == 0) atomicAdd(&g_cnt[g], 1.0f);
    }
    if (t == 0) s_gid[w] = g;
    *(float4*)&s_sum[w][d0] = a[0];
    *(float4*)&s_sum[w][d0 + 4] = a[1];
    *(float4*)&s_sum[w][256 + d0] = a[2];
    *(float4*)&s_sum[w][256 + d0 + 4] = a[3];
    __syncthreads();

    const int g0 = s_gid[0];
    bool uni = true;
#pragma unroll
    for (int i = 1; i < GW; i++) {
        const int gi = s_gid[i];
        uni &= (gi == g0 || gi < 0);
    }
    if (uni) {
        // warp w reduces dim chunk [w*64, w*64+64): lanes 0-15 sum, 16-31 sumsq
        if (g0 >= 0) {
            const int half = t >> 4;            // 0: sum, 1: sumsq
            const int d = w * 64 + (t & 15) * 4;
            float4 S = make_float4(0.f, 0.f, 0.f, 0.f);
#pragma unroll
            for (int i = 0; i < GW; i++) {
                const float4 p = *(const float4*)&s_sum[i][d];
                if (half) {
                    S.x += p.x * p.x; S.y += p.y * p.y;
                    S.z += p.z * p.z; S.w += p.w * p.w;
                } else {
                    S.x += p.x; S.y += p.y; S.z += p.z; S.w += p.w;
                }
            }
            red4((half ? g_sq : g_sum) + g0 * DIM + d, S);
        }
    } else {
        // rare mixed-graph block: each warp REDs its own node's values
        if (g >= 0) {
#pragma unroll
            for (int q = 0; q < 4; q++) {
                const int d = (q >> 1) * 256 + d0 + (q & 1) * 4;
                red4(&g_sum[g * DIM + d], a[q]);
                red4(&g_sq [g * DIM + d],
                     make_float4(a[q].x * a[q].x, a[q].y * a[q].y,
                                 a[q].z * a[q].z, a[q].w * a[q].w));
            }
        }
    }
}

// ---------------------------------------------------------------- finalize: normalize + relu
__global__ __launch_bounds__(256) void k_final(const float* __restrict__ gw,
                                               const float* __restrict__ gb,
                                               const float* __restrict__ ms,
                                               float* __restrict__ out) {
    const int idx = blockIdx.x * blockDim.x + threadIdx.x;
    if (idx >= N_NODES * 32) return;
    const int n = idx >> 5;
    const int t = idx & 31;
    const int g = g_batch[n];
    const float ic = 1.f / fmaxf(g_cnt[g], 1.f);
    const size_t nb = (size_t)n * DIM + t * 4;
#pragma unroll
    for (int q = 0; q < 4; q++) {
        const int dc = t * 4 + q * 128;
        const float4 x  = __ldcs((const float4*)(g_acc + nb + q * 128));
        const float4 sm = *(const float4*)(g_sum + g * DIM + dc);
        const float4 sq = *(const float4*)(g_sq  + g * DIM + dc);
        const float4 w4 = *(const float4*)(gw + dc);
        const float4 b4 = *(const float4*)(gb + dc);
        const float4 m4 = *(const float4*)(ms + dc);
        float4 o;
        {
            const float m = sm.x * ic, c = m * m4.x;
            const float var = sq.x * ic - 2.f * c * m + c * c;
            o.x = fmaxf(w4.x * (x.x - c) * rsqrtf(var + EPSV) + b4.x, 0.f);
        }
        {
            const float m = sm.y * ic, c = m * m4.y;
            const float var = sq.y * ic - 2.f * c * m + c * c;
            o.y = fmaxf(w4.y * (x.y - c) * rsqrtf(var + EPSV) + b4.y, 0.f);
        }
        {
            const float m = sm.z * ic, c = m * m4.z;
            const float var = sq.z * ic - 2.f * c * m + c * c;
            o.z = fmaxf(w4.z * (x.z - c) * rsqrtf(var + EPSV) + b4.z, 0.f);
        }
        {
            const float m = sm.w * ic, c = m * m4.w;
            const float var = sq.w * ic - 2.f * c * m + c * c;
            o.w = fmaxf(w4.w * (x.w - c) * rsqrtf(var + EPSV) + b4.w, 0.f);
        }
        __stcs((float4*)(out + nb + q * 128), o);
    }
}

// ---------------------------------------------------------------- launch
extern "C" void kernel_launch(void* const* d_in, const int* in_sizes, int n_in,
                              void* d_out, int out_size) {
    const float* node  = (const float*)d_in[0];
    const float* eattr = (const float*)d_in[1];
    const float* W     = (const float*)d_in[2];
    const float* b     = (const float*)d_in[3];
    const float* gw    = (const float*)d_in[4];
    const float* gb    = (const float*)d_in[5];
    const float* ms    = (const float*)d_in[6];
    const void*  ei    = d_in[7];
    const void*  batch = d_in[8];
    float* out = (float*)d_out;

    cudaFuncSetAttribute(k_gemm, cudaFuncAttributeMaxDynamicSharedMemorySize, SMEM_BYTES);

    k_init<<<(N_NODES + 255) / 256, 256>>>();
    k_convert<<<(N_EDGES + 255) / 256, 256>>>(ei, batch, eattr);
    {
        dim3 grid(DIM / 128, (N_NODES + 127) / 128);   // (4, 391)
        k_gemm<<<grid, 256, SMEM_BYTES>>>(node, W);
    }
    k_gather<<<(N_NODES + GW - 1) / GW, 256>>>(node, b);   // 6250 blocks
    k_final<<<(N_NODES * 32 + 255) / 256, 256>>>(gw, gb, ms, out);
}